// round 16
// baseline (speedup 1.0000x reference)
#include <cuda_runtime.h>
#include <cstdint>
#include <cstdio>

#define Bsz   4
#define Sln   8192
#define DIM   512
#define NH    8
#define NKV   4
#define HD    64
#define NTOK  (Bsz*Sln)          // 32768
#define KVDIM (NKV*HD)           // 256
#define GK    512
#define BK    32
#define QKVN  1024               // q(512) | k(256) | v(256)

// ---------------- scratch (device globals; no allocation allowed) ----------
__device__ float g_xn [(size_t)NTOK * DIM];    // x after rmsnorm (tf32-valued); later Y
__device__ float g_qkv[(size_t)NTOK * QKVN];   // [Q_lin(512) | K_raw(256) | V(256)]
__device__ float g_w  [QKVN * DIM];            // tf32-rounded [wq;wk;wv]
__device__ float g_wo [DIM * DIM];             // tf32-rounded wo
__device__ float g_cos[Sln * 32];
__device__ float g_sin[Sln * 32];
__device__ float g_pkv[64 * 16 * 64];
__device__ float g_pks[64 * 16 * 64];
__device__ float g_kv [16 * 64];
__device__ float g_ks [16 * 64];

// ======================= helpers =======================
__device__ __forceinline__ float f2tf(float f) {
    uint32_t o;
    asm("cvt.rn.tf32.f32 %0, %1;" : "=r"(o) : "f"(f));
    return __uint_as_float(o);
}
__device__ __forceinline__ void mma_tf32(float* d, const uint32_t* a, const uint32_t* b) {
    asm volatile(
        "mma.sync.aligned.m16n8k8.row.col.f32.tf32.tf32.f32 "
        "{%0,%1,%2,%3}, {%4,%5,%6,%7}, {%8,%9}, {%0,%1,%2,%3};"
        : "+f"(d[0]), "+f"(d[1]), "+f"(d[2]), "+f"(d[3])
        : "r"(a[0]), "r"(a[1]), "r"(a[2]), "r"(a[3]), "r"(b[0]), "r"(b[1]));
}
__device__ __forceinline__ void cp_async16(uint32_t dst, const void* src) {
    asm volatile("cp.async.cg.shared.global [%0], [%1], 16;" :: "r"(dst), "l"(src));
}
__device__ __forceinline__ void cp_commit() {
    asm volatile("cp.async.commit_group;" ::: "memory");
}
__device__ __forceinline__ void cp_wait1() {
    asm volatile("cp.async.wait_group 1;" ::: "memory");
}
__device__ __forceinline__ float elu1(float v) {
    return v > 0.f ? v + 1.f : expf(v);
}
// one x4 b16 ldmatrix = 4 8x8-tf32-equivalent fragments
#define LDSM4(r0, r1, r2, r3, addr)                                               \
    asm volatile("ldmatrix.sync.aligned.m8n8.x4.shared.b16 {%0,%1,%2,%3}, [%4];"  \
                 : "=r"(r0), "=r"(r1), "=r"(r2), "=r"(r3) : "r"(addr))

// ---------------- one-shot weight rounding/packing (single launch) -------------
__global__ __launch_bounds__(128) void prep_weights(const float* __restrict__ wq,
                                                    const float* __restrict__ wk,
                                                    const float* __restrict__ wv,
                                                    const float* __restrict__ wo) {
    int r = blockIdx.x, c4 = threadIdx.x;
    const float* src;
    float* dst;
    if (r < 512)       { src = wq + (size_t)r * DIM;          dst = g_w  + (size_t)r * DIM; }
    else if (r < 768)  { src = wk + (size_t)(r - 512) * DIM;  dst = g_w  + (size_t)r * DIM; }
    else if (r < 1024) { src = wv + (size_t)(r - 768) * DIM;  dst = g_w  + (size_t)r * DIM; }
    else               { src = wo + (size_t)(r - 1024) * DIM; dst = g_wo + (size_t)(r - 1024) * DIM; }
    float4 v = ((const float4*)src)[c4];
    v.x = f2tf(v.x); v.y = f2tf(v.y); v.z = f2tf(v.z); v.w = f2tf(v.w);
    ((float4*)dst)[c4] = v;
}

// ======================= tf32 mma.sync GEMM, cp.async 3-stage, LDSM frags ======
// C[M,N] = A[M,512] * B[N,512]^T. Block 128x128, BK=32, 128 thr = 4 warps (2m x 2n),
// warp tile 64x64. Inputs MUST be tf32-valued (pre-rounded).
// do_rope: if bn<512 apply RoPE+phi to the output pairs (Q region).
#define NSTAGE   3
#define STAGE_FL 8192
#define G_SMEM_BYTES (NSTAGE * STAGE_FL * 4)   // 98304

__global__ void __launch_bounds__(128, 2) gemm_tf32mma(const float* __restrict__ A,
                                                       const float* __restrict__ B,
                                                       float* __restrict__ C, int N,
                                                       int do_rope) {
    extern __shared__ float sm[];
    const uint32_t sbase = (uint32_t)__cvta_generic_to_shared(sm);
    const int tid  = threadIdx.x;
    const int wid  = tid >> 5, lane = tid & 31;
    const int wm   = wid & 1,  wn   = wid >> 1;
    const int bm   = blockIdx.y * 128;
    const int bn   = blockIdx.x * 128;

    const int rb  = tid >> 3;                      // base row 0..15 (+16i)
    const int gb  = tid & 7;                       // k4-group
    const int swb = ((gb ^ (rb & 7)) << 2);        // swizzled float offset in row

#define ISSUE(s, buf)                                                             \
    {                                                                             \
        const float* As = A + (size_t)(bm + rb) * GK + (s) * BK + gb * 4;         \
        const float* Bs = B + (size_t)(bn + rb) * GK + (s) * BK + gb * 4;         \
        uint32_t da = sbase + (uint32_t)((buf) * STAGE_FL + rb * 32 + swb) * 4;   \
        uint32_t db = da + 4096 * 4;                                              \
        _Pragma("unroll")                                                         \
        for (int i = 0; i < 8; i++) {                                             \
            cp_async16(da + i * (512 * 4), As + (size_t)i * 16 * GK);             \
            cp_async16(db + i * (512 * 4), Bs + (size_t)i * 16 * GK);             \
        }                                                                         \
    }

    float acc[4][8][4];
    #pragma unroll
    for (int mt = 0; mt < 4; mt++)
        #pragma unroll
        for (int nt = 0; nt < 8; nt++)
            #pragma unroll
            for (int r = 0; r < 4; r++) acc[mt][nt][r] = 0.f;

    ISSUE(0, 0); cp_commit();
    ISSUE(1, 1); cp_commit();

    // ---- ldmatrix per-lane constants ----
    // lane l = 8*lsel + row7: supplies row `row7` of matrix `lsel`.
    // matrices per x4: {rows..+0-7 @g0, rows+8-15 @g0, rows+0-7 @g1, rows+8-15 @g1}
    const int row7    = lane & 7;
    const int halfsel = (lane >> 3) & 1;     // +8 row offset for matrices 1,3
    const int gsel    = (lane >> 4) & 1;     // g1 for matrices 2,3
    uint32_t aoff[4], boff[4];
    #pragma unroll
    for (int mt = 0; mt < 4; mt++) {
        int r = wm * 64 + mt * 16 + halfsel * 8 + row7;
        aoff[mt] = (uint32_t)(r * 128);                   // bytes: r*32 floats
    }
    #pragma unroll
    for (int p = 0; p < 4; p++) {
        int n = wn * 64 + p * 16 + halfsel * 8 + row7;
        boff[p] = (uint32_t)(16384 + n * 128);            // B half offset + n*32 floats
    }

    const int lg = lane >> 2, lc = lane & 3;
    int buf = 0;
    #pragma unroll 1
    for (int s = 0; s < 16; s++) {
        cp_wait1();
        __syncthreads();
        const uint32_t sb = sbase + (uint32_t)buf * (STAGE_FL * 4);
        #pragma unroll
        for (int ks = 0; ks < 4; ks++) {
            const uint32_t off = (uint32_t)((((ks << 1) | gsel) ^ row7) << 4);
            uint32_t af[4][4], bf[8][2];
            #pragma unroll
            for (int mt = 0; mt < 4; mt++)
                LDSM4(af[mt][0], af[mt][1], af[mt][2], af[mt][3], sb + aoff[mt] + off);
            #pragma unroll
            for (int p = 0; p < 4; p++)
                LDSM4(bf[2 * p][0], bf[2 * p + 1][0], bf[2 * p][1], bf[2 * p + 1][1],
                      sb + boff[p] + off);
            #pragma unroll
            for (int mt = 0; mt < 4; mt++)
                #pragma unroll
                for (int nt = 0; nt < 8; nt++)
                    mma_tf32(acc[mt][nt], af[mt], bf[nt]);
        }
        if (s + 2 < 16) {
            int nb = buf + 2; if (nb >= 3) nb -= 3;
            ISSUE(s + 2, nb);
        }
        cp_commit();
        if (++buf == 3) buf = 0;
    }

    // epilogue
    if (do_rope && bn < 512) {
        #pragma unroll
        for (int mt = 0; mt < 4; mt++) {
            int t0 = bm + wm * 64 + mt * 16 + lg;
            int t1 = t0 + 8;
            int s0 = t0 & (Sln - 1), s1 = t1 & (Sln - 1);
            float* cr0 = C + (size_t)t0 * N + bn + wn * 64;
            float* cr1 = C + (size_t)t1 * N + bn + wn * 64;
            #pragma unroll
            for (int nt = 0; nt < 8; nt++) {
                int col = bn + wn * 64 + nt * 8 + lc * 2;
                int j = (col & 63) >> 1;
                float c0 = g_cos[s0 * 32 + j], n0 = g_sin[s0 * 32 + j];
                float c1 = g_cos[s1 * 32 + j], n1 = g_sin[s1 * 32 + j];
                float xr = acc[mt][nt][0], xi = acc[mt][nt][1];
                float yr = acc[mt][nt][2], yi = acc[mt][nt][3];
                float2 o0 = { elu1(xr * c0 - xi * n0), elu1(xr * n0 + xi * c0) };
                float2 o1 = { elu1(yr * c1 - yi * n1), elu1(yr * n1 + yi * c1) };
                *(float2*)(cr0 + nt * 8 + lc * 2) = o0;
                *(float2*)(cr1 + nt * 8 + lc * 2) = o1;
            }
        }
    } else {
        #pragma unroll
        for (int mt = 0; mt < 4; mt++) {
            float* cr0 = C + (size_t)(bm + wm * 64 + mt * 16 + lg) * N + bn + wn * 64;
            float* cr1 = cr0 + (size_t)8 * N;
            #pragma unroll
            for (int nt = 0; nt < 8; nt++) {
                float2 o0 = {acc[mt][nt][0], acc[mt][nt][1]};
                float2 o1 = {acc[mt][nt][2], acc[mt][nt][3]};
                *(float2*)(cr0 + nt * 8 + lc * 2) = o0;
                *(float2*)(cr1 + nt * 8 + lc * 2) = o1;
            }
        }
    }
#undef ISSUE
}

// ---------------- RMSNorm: one block per token; output tf32-valued -------------
__global__ __launch_bounds__(128) void rmsnorm_kernel(const float* __restrict__ x,
                                                      const float* __restrict__ w) {
    int t = blockIdx.x;
    const float4* xr = (const float4*)(x + (size_t)t * DIM);
    float4 v = xr[threadIdx.x];
    float ss = v.x*v.x + v.y*v.y + v.z*v.z + v.w*v.w;
    #pragma unroll
    for (int o = 16; o; o >>= 1) ss += __shfl_xor_sync(0xffffffffu, ss, o);
    __shared__ float sred[4];
    if ((threadIdx.x & 31) == 0) sred[threadIdx.x >> 5] = ss;
    __syncthreads();
    float tot = sred[0] + sred[1] + sred[2] + sred[3];
    float rs = rsqrtf(tot * (1.0f / DIM) + 1e-6f);
    const float4* wr = (const float4*)w;
    float4 wv = wr[threadIdx.x];
    float4 o;
    o.x = f2tf(v.x * rs * wv.x);
    o.y = f2tf(v.y * rs * wv.y);
    o.z = f2tf(v.z * rs * wv.z);
    o.w = f2tf(v.w * rs * wv.w);
    ((float4*)(g_xn + (size_t)t * DIM))[threadIdx.x] = o;
}

// ---------------- RoPE tables --------------------------------------------------
__global__ void rope_table_kernel() {
    int idx = blockIdx.x * blockDim.x + threadIdx.x;
    if (idx >= Sln * 32) return;
    int si = idx >> 5, j = idx & 31;
    float inv = powf(10000.0f, -(float)j * (1.0f / 32.0f));
    float ang = (float)si * inv;
    g_cos[idx] = cosf(ang);
    g_sin[idx] = sinf(ang);
}

// ---------------- fused K-rope+phi + KV/Ksum reduction, pass 1 -----------------
__global__ __launch_bounds__(256) void kv_reduce1_kernel() {
    int chunk = blockIdx.x >> 4;
    int bhk   = blockIdx.x & 15;
    int b = bhk >> 2, hk = bhk & 3;
    int j  = threadIdx.x & 31;
    int sl = threadIdx.x >> 5;              // 0..7, 16 rows each
    float2 akv = {0.f, 0.f}, ak = {0.f, 0.f};
    int s0 = chunk * 128 + sl * 16;
    #pragma unroll 4
    for (int i = 0; i < 16; i++) {
        int s = s0 + i;
        size_t koff = ((size_t)(b * Sln + s)) * QKVN + 512 + hk * HD + 2 * j;
        float2 kk = *(const float2*)(g_qkv + koff);
        float2 vv = *(const float2*)(g_qkv + koff + 256);
        float c  = g_cos[(s << 5) + j];
        float sn = g_sin[(s << 5) + j];
        float kr = elu1(kk.x * c - kk.y * sn);
        float ki = elu1(kk.x * sn + kk.y * c);
        akv.x += kr * vv.x; akv.y += ki * vv.y;
        ak.x  += kr;        ak.y  += ki;
    }
    __shared__ float2 skv[256], sks[256];
    skv[threadIdx.x] = akv; sks[threadIdx.x] = ak;
    __syncthreads();
    if (sl == 0) {
        #pragma unroll
        for (int t2 = 1; t2 < 8; t2++) {
            float2 a = skv[t2 * 32 + j], b2 = sks[t2 * 32 + j];
            akv.x += a.x; akv.y += a.y;
            ak.x  += b2.x; ak.y += b2.y;
        }
        float* okv = g_pkv + (size_t)blockIdx.x * 64 + 2 * j;
        float* oks = g_pks + (size_t)blockIdx.x * 64 + 2 * j;
        okv[0] = akv.x; okv[1] = akv.y;
        oks[0] = ak.x;  oks[1] = ak.y;
    }
}

// ---------------- pass 2 -------------------------------------------------------
__global__ void kv_reduce2_kernel() {
    int bhk = blockIdx.x;
    int d = threadIdx.x;
    float akv = 0.f, ak = 0.f;
    #pragma unroll 8
    for (int c = 0; c < 64; c++) {
        akv += g_pkv[((c << 4) + bhk) * 64 + d];
        ak  += g_pks[((c << 4) + bhk) * 64 + d];
    }
    g_kv[bhk * 64 + d] = akv;
    g_ks[bhk * 64 + d] = ak;
}

// ---------------- per-token normalize -> Y (tf32-valued) into g_xn -------------
__global__ __launch_bounds__(256) void attn_out_kernel() {
    int t = blockIdx.x;
    int h = threadIdx.x >> 5;
    int lane = threadIdx.x & 31;
    int b = t >> 13;
    int hk = h >> 1;
    size_t qoff = (size_t)t * QKVN + h * HD;
    float q0 = g_qkv[qoff + lane];
    float q1 = g_qkv[qoff + 32 + lane];
    int koff = (b * 4 + hk) * 64;
    float z = q0 * g_ks[koff + lane] + q1 * g_ks[koff + 32 + lane];
    #pragma unroll
    for (int o = 16; o; o >>= 1) z += __shfl_xor_sync(0xffffffffu, z, o);
    float inv = 1.0f / (z + 1e-6f);
    size_t yoff = (size_t)t * DIM + h * HD;
    g_xn[yoff + lane]      = f2tf(q0 * g_kv[koff + lane]      * inv);
    g_xn[yoff + 32 + lane] = f2tf(q1 * g_kv[koff + 32 + lane] * inv);
}

// ---------------- host launcher -----------------------------------------------
extern "C" void kernel_launch(void* const* d_in, const int* in_sizes, int n_in,
                              void* d_out, int out_size) {
    (void)in_sizes; (void)n_in; (void)out_size;
    const float* x  = (const float*)d_in[0];
    const float* nw = (const float*)d_in[1];
    const float* wq = (const float*)d_in[2];
    const float* wk = (const float*)d_in[3];
    const float* wv = (const float*)d_in[4];
    const float* wo = (const float*)d_in[5];
    float* out = (float*)d_out;

    float *p_xn, *p_qkv, *p_w, *p_wo;
    cudaGetSymbolAddress((void**)&p_xn,  g_xn);
    cudaGetSymbolAddress((void**)&p_qkv, g_qkv);
    cudaGetSymbolAddress((void**)&p_w,   g_w);
    cudaGetSymbolAddress((void**)&p_wo,  g_wo);

    static cudaStream_t s_side = nullptr;
    static cudaEvent_t evFork = nullptr, evJoin = nullptr;
    if (!s_side) {
        cudaFuncSetAttribute(gemm_tf32mma, cudaFuncAttributeMaxDynamicSharedMemorySize,
                             G_SMEM_BYTES);
        cudaStreamCreateWithFlags(&s_side, cudaStreamNonBlocking);
        cudaEventCreateWithFlags(&evFork, cudaEventDisableTiming);
        cudaEventCreateWithFlags(&evJoin, cudaEventDisableTiming);
    }

    // fork: preamble on side stream overlaps rmsnorm on main stream
    cudaEventRecord(evFork, 0);
    cudaStreamWaitEvent(s_side, evFork, 0);
    rope_table_kernel<<<(Sln * 32 + 255) / 256, 256, 0, s_side>>>();
    prep_weights<<<1536, 128, 0, s_side>>>(wq, wk, wv, wo);
    cudaEventRecord(evJoin, s_side);

    rmsnorm_kernel<<<NTOK, 128>>>(x, nw);
    cudaStreamWaitEvent(0, evJoin, 0);

    // fused QKV GEMM (+RoPE+phi on Q region in epilogue)
    gemm_tf32mma<<<dim3(QKVN / 128, NTOK / 128), 128, G_SMEM_BYTES>>>(p_xn, p_w, p_qkv, QKVN, 1);
    kv_reduce1_kernel<<<64 * 16, 256>>>();
    kv_reduce2_kernel<<<16, 64>>>();
    attn_out_kernel<<<NTOK, 256>>>();
    // output GEMM
    gemm_tf32mma<<<dim3(DIM / 128, NTOK / 128), 128, G_SMEM_BYTES>>>(p_xn, p_wo, out, DIM, 0);
}

// round 17
// speedup vs baseline: 1.0787x; 1.0787x over previous
#include <cuda_runtime.h>
#include <cstdint>
#include <cstdio>

#define Bsz   4
#define Sln   8192
#define DIM   512
#define NH    8
#define NKV   4
#define HD    64
#define NTOK  (Bsz*Sln)          // 32768
#define KVDIM (NKV*HD)           // 256
#define GK    512
#define BK    32
#define QKVN  1024               // q(512) | k(256) | v(256)

// ---------------- scratch (device globals; no allocation allowed) ----------
__device__ float g_xn [(size_t)NTOK * DIM];    // x after rmsnorm (tf32-valued); later Y
__device__ float g_qkv[(size_t)NTOK * QKVN];   // [Q_lin(512) | K_raw(256) | V(256)]
__device__ float g_w  [QKVN * DIM];            // tf32-rounded [wq;wk;wv]
__device__ float g_wo [DIM * DIM];             // tf32-rounded wo
__device__ float g_cos[Sln * 32];
__device__ float g_sin[Sln * 32];
__device__ float g_pkv[64 * 16 * 64];
__device__ float g_pks[64 * 16 * 64];
__device__ float g_kv [16 * 64];
__device__ float g_ks [16 * 64];

// ======================= helpers =======================
__device__ __forceinline__ float f2tf(float f) {
    uint32_t o;
    asm("cvt.rn.tf32.f32 %0, %1;" : "=r"(o) : "f"(f));
    return __uint_as_float(o);
}
__device__ __forceinline__ void mma_tf32(float* d, const uint32_t* a, const uint32_t* b) {
    asm volatile(
        "mma.sync.aligned.m16n8k8.row.col.f32.tf32.tf32.f32 "
        "{%0,%1,%2,%3}, {%4,%5,%6,%7}, {%8,%9}, {%0,%1,%2,%3};"
        : "+f"(d[0]), "+f"(d[1]), "+f"(d[2]), "+f"(d[3])
        : "r"(a[0]), "r"(a[1]), "r"(a[2]), "r"(a[3]), "r"(b[0]), "r"(b[1]));
}
__device__ __forceinline__ void cp_async16(uint32_t dst, const void* src) {
    asm volatile("cp.async.cg.shared.global [%0], [%1], 16;" :: "r"(dst), "l"(src));
}
__device__ __forceinline__ void cp_commit() {
    asm volatile("cp.async.commit_group;" ::: "memory");
}
__device__ __forceinline__ void cp_wait1() {
    asm volatile("cp.async.wait_group 1;" ::: "memory");
}
__device__ __forceinline__ float elu1(float v) {
    return v > 0.f ? v + 1.f : expf(v);
}

// ---------------- one-shot weight rounding/packing (single launch) -------------
__global__ __launch_bounds__(128) void prep_weights(const float* __restrict__ wq,
                                                    const float* __restrict__ wk,
                                                    const float* __restrict__ wv,
                                                    const float* __restrict__ wo) {
    int r = blockIdx.x, c4 = threadIdx.x;
    const float* src;
    float* dst;
    if (r < 512)       { src = wq + (size_t)r * DIM;          dst = g_w  + (size_t)r * DIM; }
    else if (r < 768)  { src = wk + (size_t)(r - 512) * DIM;  dst = g_w  + (size_t)r * DIM; }
    else if (r < 1024) { src = wv + (size_t)(r - 768) * DIM;  dst = g_w  + (size_t)r * DIM; }
    else               { src = wo + (size_t)(r - 1024) * DIM; dst = g_wo + (size_t)(r - 1024) * DIM; }
    float4 v = ((const float4*)src)[c4];
    v.x = f2tf(v.x); v.y = f2tf(v.y); v.z = f2tf(v.z); v.w = f2tf(v.w);
    ((float4*)dst)[c4] = v;
}

// ======================= tf32 mma.sync GEMM, cp.async 3-stage (R14 core) =======
// C[M,N] = A[M,512] * B[N,512]^T. Block 128x128, BK=32, 128 thr = 4 warps (2m x 2n),
// warp tile 64x64. Inputs MUST be tf32-valued (pre-rounded).
// do_rope: if bn<512 apply RoPE+phi to the output pairs (Q region).
#define NSTAGE   3
#define STAGE_FL 8192
#define G_SMEM_BYTES (NSTAGE * STAGE_FL * 4)   // 98304

__global__ void __launch_bounds__(128, 2) gemm_tf32mma(const float* __restrict__ A,
                                                       const float* __restrict__ B,
                                                       float* __restrict__ C, int N,
                                                       int do_rope) {
    extern __shared__ float sm[];
    const uint32_t sbase = (uint32_t)__cvta_generic_to_shared(sm);
    const int tid  = threadIdx.x;
    const int wid  = tid >> 5, lane = tid & 31;
    const int wm   = wid & 1,  wn   = wid >> 1;
    const int bm   = blockIdx.y * 128;
    const int bn   = blockIdx.x * 128;

    const int rb  = tid >> 3;                      // base row 0..15 (+16i)
    const int gb  = tid & 7;                       // k4-group
    const int swb = ((gb ^ (rb & 7)) << 2);        // swizzled float offset in row

#define ISSUE(s, buf)                                                             \
    {                                                                             \
        const float* As = A + (size_t)(bm + rb) * GK + (s) * BK + gb * 4;         \
        const float* Bs = B + (size_t)(bn + rb) * GK + (s) * BK + gb * 4;         \
        uint32_t da = sbase + (uint32_t)((buf) * STAGE_FL + rb * 32 + swb) * 4;   \
        uint32_t db = da + 4096 * 4;                                              \
        _Pragma("unroll")                                                         \
        for (int i = 0; i < 8; i++) {                                             \
            cp_async16(da + i * (512 * 4), As + (size_t)i * 16 * GK);             \
            cp_async16(db + i * (512 * 4), Bs + (size_t)i * 16 * GK);             \
        }                                                                         \
    }

    float acc[4][8][4];
    #pragma unroll
    for (int mt = 0; mt < 4; mt++)
        #pragma unroll
        for (int nt = 0; nt < 8; nt++)
            #pragma unroll
            for (int r = 0; r < 4; r++) acc[mt][nt][r] = 0.f;

    ISSUE(0, 0); cp_commit();
    ISSUE(1, 1); cp_commit();

    const int lg = lane >> 2, lc = lane & 3;
    int buf = 0;
    #pragma unroll 1
    for (int s = 0; s < 16; s++) {
        cp_wait1();
        __syncthreads();
        const float* sA = sm + buf * STAGE_FL;
        const float* sB = sA + 4096;
        #pragma unroll
        for (int ks = 0; ks < 4; ks++) {
            const int g0 = 2 * ks, g1 = 2 * ks + 1;
            uint32_t af[4][4], bf[8][2];
            #pragma unroll
            for (int mt = 0; mt < 4; mt++) {
                int r = wm * 64 + mt * 16 + lg;
                int s0 = ((g0 ^ (r & 7)) << 2) + lc;
                int s1 = ((g1 ^ (r & 7)) << 2) + lc;
                af[mt][0] = __float_as_uint(sA[r * 32 + s0]);
                af[mt][1] = __float_as_uint(sA[(r + 8) * 32 + s0]);
                af[mt][2] = __float_as_uint(sA[r * 32 + s1]);
                af[mt][3] = __float_as_uint(sA[(r + 8) * 32 + s1]);
            }
            #pragma unroll
            for (int nt = 0; nt < 8; nt++) {
                int n = wn * 64 + nt * 8 + lg;
                bf[nt][0] = __float_as_uint(sB[n * 32 + ((g0 ^ (n & 7)) << 2) + lc]);
                bf[nt][1] = __float_as_uint(sB[n * 32 + ((g1 ^ (n & 7)) << 2) + lc]);
            }
            #pragma unroll
            for (int mt = 0; mt < 4; mt++)
                #pragma unroll
                for (int nt = 0; nt < 8; nt++)
                    mma_tf32(acc[mt][nt], af[mt], bf[nt]);
        }
        if (s + 2 < 16) {
            int nb = buf + 2; if (nb >= 3) nb -= 3;
            ISSUE(s + 2, nb);
        }
        cp_commit();
        if (++buf == 3) buf = 0;
    }

    // epilogue
    if (do_rope && bn < 512) {
        #pragma unroll
        for (int mt = 0; mt < 4; mt++) {
            int t0 = bm + wm * 64 + mt * 16 + lg;
            int t1 = t0 + 8;
            int s0 = t0 & (Sln - 1), s1 = t1 & (Sln - 1);
            float* cr0 = C + (size_t)t0 * N + bn + wn * 64;
            float* cr1 = C + (size_t)t1 * N + bn + wn * 64;
            #pragma unroll
            for (int nt = 0; nt < 8; nt++) {
                int col = bn + wn * 64 + nt * 8 + lc * 2;
                int j = (col & 63) >> 1;
                float c0 = g_cos[s0 * 32 + j], n0 = g_sin[s0 * 32 + j];
                float c1 = g_cos[s1 * 32 + j], n1 = g_sin[s1 * 32 + j];
                float xr = acc[mt][nt][0], xi = acc[mt][nt][1];
                float yr = acc[mt][nt][2], yi = acc[mt][nt][3];
                float2 o0 = { elu1(xr * c0 - xi * n0), elu1(xr * n0 + xi * c0) };
                float2 o1 = { elu1(yr * c1 - yi * n1), elu1(yr * n1 + yi * c1) };
                *(float2*)(cr0 + nt * 8 + lc * 2) = o0;
                *(float2*)(cr1 + nt * 8 + lc * 2) = o1;
            }
        }
    } else {
        #pragma unroll
        for (int mt = 0; mt < 4; mt++) {
            float* cr0 = C + (size_t)(bm + wm * 64 + mt * 16 + lg) * N + bn + wn * 64;
            float* cr1 = cr0 + (size_t)8 * N;
            #pragma unroll
            for (int nt = 0; nt < 8; nt++) {
                float2 o0 = {acc[mt][nt][0], acc[mt][nt][1]};
                float2 o1 = {acc[mt][nt][2], acc[mt][nt][3]};
                *(float2*)(cr0 + nt * 8 + lc * 2) = o0;
                *(float2*)(cr1 + nt * 8 + lc * 2) = o1;
            }
        }
    }
#undef ISSUE
}

// ---------------- RMSNorm: one block per token; output tf32-valued -------------
__global__ __launch_bounds__(128) void rmsnorm_kernel(const float* __restrict__ x,
                                                      const float* __restrict__ w) {
    int t = blockIdx.x;
    const float4* xr = (const float4*)(x + (size_t)t * DIM);
    float4 v = xr[threadIdx.x];
    float ss = v.x*v.x + v.y*v.y + v.z*v.z + v.w*v.w;
    #pragma unroll
    for (int o = 16; o; o >>= 1) ss += __shfl_xor_sync(0xffffffffu, ss, o);
    __shared__ float sred[4];
    if ((threadIdx.x & 31) == 0) sred[threadIdx.x >> 5] = ss;
    __syncthreads();
    float tot = sred[0] + sred[1] + sred[2] + sred[3];
    float rs = rsqrtf(tot * (1.0f / DIM) + 1e-6f);
    const float4* wr = (const float4*)w;
    float4 wv = wr[threadIdx.x];
    float4 o;
    o.x = f2tf(v.x * rs * wv.x);
    o.y = f2tf(v.y * rs * wv.y);
    o.z = f2tf(v.z * rs * wv.z);
    o.w = f2tf(v.w * rs * wv.w);
    ((float4*)(g_xn + (size_t)t * DIM))[threadIdx.x] = o;
}

// ---------------- RoPE tables --------------------------------------------------
__global__ void rope_table_kernel() {
    int idx = blockIdx.x * blockDim.x + threadIdx.x;
    if (idx >= Sln * 32) return;
    int si = idx >> 5, j = idx & 31;
    float inv = powf(10000.0f, -(float)j * (1.0f / 32.0f));
    float ang = (float)si * inv;
    g_cos[idx] = cosf(ang);
    g_sin[idx] = sinf(ang);
}

// ---------------- fused K-rope+phi + KV/Ksum reduction, pass 1 -----------------
__global__ __launch_bounds__(256) void kv_reduce1_kernel() {
    int chunk = blockIdx.x >> 4;
    int bhk   = blockIdx.x & 15;
    int b = bhk >> 2, hk = bhk & 3;
    int j  = threadIdx.x & 31;
    int sl = threadIdx.x >> 5;              // 0..7, 16 rows each
    float2 akv = {0.f, 0.f}, ak = {0.f, 0.f};
    int s0 = chunk * 128 + sl * 16;
    #pragma unroll 4
    for (int i = 0; i < 16; i++) {
        int s = s0 + i;
        size_t koff = ((size_t)(b * Sln + s)) * QKVN + 512 + hk * HD + 2 * j;
        float2 kk = *(const float2*)(g_qkv + koff);
        float2 vv = *(const float2*)(g_qkv + koff + 256);
        float c  = g_cos[(s << 5) + j];
        float sn = g_sin[(s << 5) + j];
        float kr = elu1(kk.x * c - kk.y * sn);
        float ki = elu1(kk.x * sn + kk.y * c);
        akv.x += kr * vv.x; akv.y += ki * vv.y;
        ak.x  += kr;        ak.y  += ki;
    }
    __shared__ float2 skv[256], sks[256];
    skv[threadIdx.x] = akv; sks[threadIdx.x] = ak;
    __syncthreads();
    if (sl == 0) {
        #pragma unroll
        for (int t2 = 1; t2 < 8; t2++) {
            float2 a = skv[t2 * 32 + j], b2 = sks[t2 * 32 + j];
            akv.x += a.x; akv.y += a.y;
            ak.x  += b2.x; ak.y += b2.y;
        }
        float* okv = g_pkv + (size_t)blockIdx.x * 64 + 2 * j;
        float* oks = g_pks + (size_t)blockIdx.x * 64 + 2 * j;
        okv[0] = akv.x; okv[1] = akv.y;
        oks[0] = ak.x;  oks[1] = ak.y;
    }
}

// ---------------- pass 2 -------------------------------------------------------
__global__ void kv_reduce2_kernel() {
    int bhk = blockIdx.x;
    int d = threadIdx.x;
    float akv = 0.f, ak = 0.f;
    #pragma unroll 8
    for (int c = 0; c < 64; c++) {
        akv += g_pkv[((c << 4) + bhk) * 64 + d];
        ak  += g_pks[((c << 4) + bhk) * 64 + d];
    }
    g_kv[bhk * 64 + d] = akv;
    g_ks[bhk * 64 + d] = ak;
}

// ---------------- per-token normalize -> Y (tf32-valued) into g_xn -------------
__global__ __launch_bounds__(256) void attn_out_kernel() {
    int t = blockIdx.x;
    int h = threadIdx.x >> 5;
    int lane = threadIdx.x & 31;
    int b = t >> 13;
    int hk = h >> 1;
    size_t qoff = (size_t)t * QKVN + h * HD;
    float q0 = g_qkv[qoff + lane];
    float q1 = g_qkv[qoff + 32 + lane];
    int koff = (b * 4 + hk) * 64;
    float z = q0 * g_ks[koff + lane] + q1 * g_ks[koff + 32 + lane];
    #pragma unroll
    for (int o = 16; o; o >>= 1) z += __shfl_xor_sync(0xffffffffu, z, o);
    float inv = 1.0f / (z + 1e-6f);
    size_t yoff = (size_t)t * DIM + h * HD;
    g_xn[yoff + lane]      = f2tf(q0 * g_kv[koff + lane]      * inv);
    g_xn[yoff + 32 + lane] = f2tf(q1 * g_kv[koff + 32 + lane] * inv);
}

// ---------------- host launcher -----------------------------------------------
extern "C" void kernel_launch(void* const* d_in, const int* in_sizes, int n_in,
                              void* d_out, int out_size) {
    (void)in_sizes; (void)n_in; (void)out_size;
    const float* x  = (const float*)d_in[0];
    const float* nw = (const float*)d_in[1];
    const float* wq = (const float*)d_in[2];
    const float* wk = (const float*)d_in[3];
    const float* wv = (const float*)d_in[4];
    const float* wo = (const float*)d_in[5];
    float* out = (float*)d_out;

    float *p_xn, *p_qkv, *p_w, *p_wo;
    cudaGetSymbolAddress((void**)&p_xn,  g_xn);
    cudaGetSymbolAddress((void**)&p_qkv, g_qkv);
    cudaGetSymbolAddress((void**)&p_w,   g_w);
    cudaGetSymbolAddress((void**)&p_wo,  g_wo);

    static cudaStream_t s_side = nullptr;
    static cudaEvent_t evFork = nullptr, evJoin = nullptr;
    if (!s_side) {
        cudaFuncSetAttribute(gemm_tf32mma, cudaFuncAttributeMaxDynamicSharedMemorySize,
                             G_SMEM_BYTES);
        cudaStreamCreateWithFlags(&s_side, cudaStreamNonBlocking);
        cudaEventCreateWithFlags(&evFork, cudaEventDisableTiming);
        cudaEventCreateWithFlags(&evJoin, cudaEventDisableTiming);
    }

    // fork: preamble on side stream overlaps rmsnorm on main stream
    cudaEventRecord(evFork, 0);
    cudaStreamWaitEvent(s_side, evFork, 0);
    rope_table_kernel<<<(Sln * 32 + 255) / 256, 256, 0, s_side>>>();
    prep_weights<<<1536, 128, 0, s_side>>>(wq, wk, wv, wo);
    cudaEventRecord(evJoin, s_side);

    rmsnorm_kernel<<<NTOK, 128>>>(x, nw);
    cudaStreamWaitEvent(0, evJoin, 0);

    // fused QKV GEMM (+RoPE+phi on Q region in epilogue)
    gemm_tf32mma<<<dim3(QKVN / 128, NTOK / 128), 128, G_SMEM_BYTES>>>(p_xn, p_w, p_qkv, QKVN, 1);
    kv_reduce1_kernel<<<64 * 16, 256>>>();
    kv_reduce2_kernel<<<16, 64>>>();
    attn_out_kernel<<<NTOK, 256>>>();
    // output GEMM
    gemm_tf32mma<<<dim3(DIM / 128, NTOK / 128), 128, G_SMEM_BYTES>>>(p_xn, p_wo, out, DIM, 0);
}